// round 13
// baseline (speedup 1.0000x reference)
#include <cuda_runtime.h>
#include <cuda_fp16.h>
#include <cstdint>

#define N_NODES 8192
#define M_NBR   16
#define F_NODE  128
#define HID     512

// ---------------- scratch (__device__ globals; no allocations) ----------------
__device__ __half g_HA[N_NODES * HID];   // fp16 GEMM input (spmm output)
__device__ float  g_XF[N_NODES * HID];   // fp32 GEMM output (spmm input)
__device__ float  g_dinv[N_NODES];
#define WOFF_1 0
#define WOFF_2 (HID * HID)
#define WOFF_3 (2 * HID * HID)
__device__ __half g_W[3 * HID * HID];    // W1t/W2t/W3t, [N][K] K-major
__device__ __half g_WaT[HID * F_NODE];   // (W_emb@W1)^T, [512][128] K-major
__device__ float  g_c1[HID];             // b_emb @ W1
__device__ float  g_zero[HID];           // zero bias (never written)

// ---------------- PTX helpers (compute_103-safe) ----------------
__device__ __forceinline__ uint32_t smem_to_u32(const void* p) {
    uint32_t a;
    asm("{ .reg .u64 t; cvta.to.shared.u64 t, %1; cvt.u32.u64 %0, t; }" : "=r"(a) : "l"(p));
    return a;
}
__device__ __forceinline__ void cp_async16(uint32_t saddr, const void* gptr) {
    asm volatile("cp.async.cg.shared.global [%0], [%1], 16;" :: "r"(saddr), "l"(gptr));
}
#define CP_COMMIT() asm volatile("cp.async.commit_group;" ::: "memory")
#define CP_WAIT0()  asm volatile("cp.async.wait_group 0;" ::: "memory")
#define CP_WAIT1()  asm volatile("cp.async.wait_group 1;" ::: "memory")

__device__ __forceinline__ void ldsm_x4(uint32_t& r0, uint32_t& r1, uint32_t& r2,
                                        uint32_t& r3, uint32_t addr) {
    asm volatile("ldmatrix.sync.aligned.m8n8.x4.shared.b16 {%0,%1,%2,%3}, [%4];"
                 : "=r"(r0), "=r"(r1), "=r"(r2), "=r"(r3) : "r"(addr));
}
__device__ __forceinline__ void mma16816(float* d, const uint32_t* a, const uint32_t* b) {
    asm volatile(
        "mma.sync.aligned.m16n8k16.row.col.f32.f16.f16.f32 "
        "{%0,%1,%2,%3}, {%4,%5,%6,%7}, {%8,%9}, {%0,%1,%2,%3};"
        : "+f"(d[0]), "+f"(d[1]), "+f"(d[2]), "+f"(d[3])
        : "r"(a[0]), "r"(a[1]), "r"(a[2]), "r"(a[3]), "r"(b[0]), "r"(b[1]));
}

// ---------------------------------------------------------------------------
// Fused preprocessing (one launch):
//   [0,32)          deg -> dinv
//   [32,1056)       node_in fp32 -> g_HA fp16
//   [1056,1824)     W1/W2/W3 transpose -> g_W
//   [1824,1856)     WaT = (W_emb @ W1)^T  (fp32 compute, fp16 store)
//   [1856,1858)     c1 = b_emb @ W1  (fp32)
// ---------------------------------------------------------------------------
#define PREP_DEG    32
#define PREP_CONV   1024
#define PREP_W3     768
#define PREP_WA     32
#define PREP_C1     2
#define PREP_BLOCKS (PREP_DEG + PREP_CONV + PREP_W3 + PREP_WA + PREP_C1)

__device__ __forceinline__ void wconv_tile(const float* __restrict__ W, int K, int N,
                                           __half* __restrict__ o,
                                           int n0, int k0, int tx, int ty,
                                           float (*tile)[33]) {
#pragma unroll
    for (int r = 0; r < 4; r++) {
        int k = k0 + ty + r * 8;
        tile[ty + r * 8][tx] = W[(size_t)k * N + n0 + tx];
    }
    __syncthreads();
#pragma unroll
    for (int r = 0; r < 4; r++) {
        int n = ty + r * 8;
        o[(size_t)(n0 + n) * K + k0 + tx] = __float2half_rn(tile[tx][n]);
    }
}

__global__ __launch_bounds__(256) void prep_kernel(const int* __restrict__ idx,
                                                   const float* __restrict__ node_in,
                                                   const float* __restrict__ W_emb,
                                                   const float* __restrict__ b_emb,
                                                   const float* __restrict__ W1,
                                                   const float* __restrict__ W2,
                                                   const float* __restrict__ W3) {
    __shared__ float tile[32][33];
    const int b = blockIdx.x;
    const int tid = threadIdx.x;

    if (b < PREP_DEG) {
        int i = b * 256 + tid;
        int cnt = 1;
#pragma unroll
        for (int k = 0; k < M_NBR; k++) cnt += (idx[i * M_NBR + k] >= 0) ? 1 : 0;
        g_dinv[i] = rsqrtf((float)cnt);
    } else if (b < PREP_DEG + PREP_CONV) {
        int c4 = (b - PREP_DEG) * 256 + tid;
        float4 v = ((const float4*)node_in)[c4];
        __half2 h0 = __floats2half2_rn(v.x, v.y);
        __half2 h1 = __floats2half2_rn(v.z, v.w);
        uint2 o;
        o.x = *(uint32_t*)&h0;
        o.y = *(uint32_t*)&h1;
        ((uint2*)g_HA)[c4] = o;
    } else if (b < PREP_DEG + PREP_CONV + PREP_W3) {
        int t = b - (PREP_DEG + PREP_CONV);
        int z = t >> 8;
        int tt = t & 255;
        int n0 = (tt & 15) * 32, k0 = (tt >> 4) * 32;
        const float* W = (z == 0) ? W1 : (z == 1) ? W2 : W3;
        wconv_tile(W, HID, HID, g_W + (size_t)z * HID * HID, n0, k0,
                   tid & 31, tid >> 5, tile);
    } else if (b < PREP_DEG + PREP_CONV + PREP_W3 + PREP_WA) {
        // WaT[n][k] = fp16( sum_m W_emb[k][m] * W1[m][n] ), k-tile of 4
        int k0 = (b - (PREP_DEG + PREP_CONV + PREP_W3)) * 4;
        const int n = tid;           // and n+256
        float acc[4][2];
#pragma unroll
        for (int kk = 0; kk < 4; kk++) { acc[kk][0] = 0.0f; acc[kk][1] = 0.0f; }
        for (int m = 0; m < HID; m++) {
            float x0 = W1[(size_t)m * HID + n];
            float x1 = W1[(size_t)m * HID + n + 256];
#pragma unroll
            for (int kk = 0; kk < 4; kk++) {
                float w = __ldg(&W_emb[(size_t)(k0 + kk) * HID + m]);
                acc[kk][0] += w * x0;
                acc[kk][1] += w * x1;
            }
        }
#pragma unroll
        for (int kk = 0; kk < 4; kk++) {
            g_WaT[(size_t)n * F_NODE + k0 + kk] = __float2half_rn(acc[kk][0]);
            g_WaT[(size_t)(n + 256) * F_NODE + k0 + kk] = __float2half_rn(acc[kk][1]);
        }
    } else {
        // c1[n] = sum_k b_emb[k] * W1[k][n]
        int n = (b - (PREP_DEG + PREP_CONV + PREP_W3 + PREP_WA)) * 256 + tid;
        float c = 0.0f;
        for (int k = 0; k < HID; k++) c += b_emb[k] * W1[(size_t)k * HID + n];
        g_c1[n] = c;
    }
}

// ---------------------------------------------------------------------------
// SpMM finisher (fp32 in, fp16/fp32 out):
//   out[i,:] = (relu?)( di*(di*X[i,:] + sum dj*X[j,:]) + bias )
// 256 thr = 4 rows x 64 lanes; 32B (8 floats) per lane. No conversions in loop.
// ---------------------------------------------------------------------------
template <bool RELU, bool HALF_OUT>
__global__ __launch_bounds__(256) void spmm_kernel(const int* __restrict__ idx,
                                                   const float* __restrict__ Xin,
                                                   const float* __restrict__ bias,
                                                   void* __restrict__ Out) {
    const int rloc = threadIdx.x >> 6;
    const int t64 = threadIdx.x & 63;
    const int i = blockIdx.x * 4 + rloc;

    __shared__ int s_j[4][M_NBR];
    __shared__ float s_dj[4][M_NBR];
    if (t64 < M_NBR) {
        int j = idx[i * M_NBR + t64];
        s_j[rloc][t64] = (j >= 0) ? j : 0;
        s_dj[rloc][t64] = (j >= 0) ? g_dinv[j] : 0.0f;
    }
    __syncthreads();

    const float di = g_dinv[i];
    float acc[8];
    {
        const float4* row = (const float4*)(Xin + (size_t)i * HID);
        float4 v0 = row[t64 * 2];
        float4 v1 = row[t64 * 2 + 1];
        acc[0] = v0.x * di; acc[1] = v0.y * di;
        acc[2] = v0.z * di; acc[3] = v0.w * di;
        acc[4] = v1.x * di; acc[5] = v1.y * di;
        acc[6] = v1.z * di; acc[7] = v1.w * di;
    }

#pragma unroll
    for (int k = 0; k < M_NBR; k++) {
        const int j = s_j[rloc][k];
        const float dj = s_dj[rloc][k];
        const float4* row = (const float4*)(Xin + (size_t)j * HID);
        float4 v0 = row[t64 * 2];
        float4 v1 = row[t64 * 2 + 1];
        acc[0] += dj * v0.x; acc[1] += dj * v0.y;
        acc[2] += dj * v0.z; acc[3] += dj * v0.w;
        acc[4] += dj * v1.x; acc[5] += dj * v1.y;
        acc[6] += dj * v1.z; acc[7] += dj * v1.w;
    }

    const int c0 = t64 * 8;
    float4 bv0 = *(const float4*)&bias[c0];
    float4 bv1 = *(const float4*)&bias[c0 + 4];
    acc[0] = acc[0] * di + bv0.x; acc[1] = acc[1] * di + bv0.y;
    acc[2] = acc[2] * di + bv0.z; acc[3] = acc[3] * di + bv0.w;
    acc[4] = acc[4] * di + bv1.x; acc[5] = acc[5] * di + bv1.y;
    acc[6] = acc[6] * di + bv1.z; acc[7] = acc[7] * di + bv1.w;
    if (RELU) {
#pragma unroll
        for (int q = 0; q < 8; q++) acc[q] = fmaxf(acc[q], 0.0f);
    }

    if (HALF_OUT) {
        uint4 o;
        __half2 h0 = __floats2half2_rn(acc[0], acc[1]);
        __half2 h1 = __floats2half2_rn(acc[2], acc[3]);
        __half2 h2 = __floats2half2_rn(acc[4], acc[5]);
        __half2 h3 = __floats2half2_rn(acc[6], acc[7]);
        o.x = *(uint32_t*)&h0;
        o.y = *(uint32_t*)&h1;
        o.z = *(uint32_t*)&h2;
        o.w = *(uint32_t*)&h3;
        ((uint4*)((__half*)Out + (size_t)i * HID))[t64] = o;
    } else {
        float* of = (float*)Out + (size_t)i * HID + c0;
        *(float4*)of = make_float4(acc[0], acc[1], acc[2], acc[3]);
        *(float4*)(of + 4) = make_float4(acc[4], acc[5], acc[6], acc[7]);
    }
}

// ---------------------------------------------------------------------------
// fp16 HMMA GEMM: C[M x 512](fp32) = A[M x K] * B[512 x K]^T + bias
// BM=128 BN=128 BK=64, 256 thr, warp grid 2x4 (warp tile 64x32),
// 3-stage cp.async, one __syncthreads per k-iter (R9 inner loop).
// ---------------------------------------------------------------------------
#define BM 128
#define BN 128
#define BK 64
#define GTHR 256
#define ROWB 144                       // 64*2 + 16 pad bytes
#define STAGE_B (2 * BM * ROWB)        // 36864 B per stage
#define GSMEM   (3 * STAGE_B)          // 110592 B

template <int K>
__global__ __launch_bounds__(GTHR, 2)
void gemm_hmma_kernel(const __half* __restrict__ A,
                      const __half* __restrict__ B,
                      const float* __restrict__ bias,
                      float* __restrict__ C) {
    extern __shared__ __align__(16) char dynsmem[];

    const int tid = threadIdx.x;
    const int lane = tid & 31;
    const int wid = tid >> 5;
    const int warp_m = wid >> 2;
    const int warp_n = wid & 3;
    const int m0 = blockIdx.y * BM;
    const int n0 = blockIdx.x * BN;

    uint32_t sA[3], sB[3];
#pragma unroll
    for (int s = 0; s < 3; s++) {
        sA[s] = smem_to_u32(dynsmem + s * STAGE_B);
        sB[s] = sA[s] + BM * ROWB;
    }

    float acc[4][4][4];
#pragma unroll
    for (int i = 0; i < 4; i++)
#pragma unroll
        for (int j = 0; j < 4; j++)
#pragma unroll
            for (int q = 0; q < 4; q++) acc[i][j][q] = 0.0f;

    constexpr int KT = K / BK;

    const int mat = lane >> 3;
    const int mrow = lane & 7;
    const int a_row = warp_m * 64 + ((mat & 1) << 3) + mrow;
    const int a_koff = (mat >> 1) << 3;
    const int b_row = warp_n * 32 + ((mat >> 1) << 3) + mrow;
    const int b_koff = (mat & 1) << 3;

    const int lr = tid >> 3;        // 0..31
    const int lc = tid & 7;         // 0..7

#define LOAD_STAGE(kt, buf)                                                     \
    do {                                                                        \
        const int kk_ = (kt) * BK;                                              \
        _Pragma("unroll")                                                       \
        for (int s_ = 0; s_ < 4; s_++) {                                        \
            int r_ = lr + s_ * 32;                                              \
            cp_async16(sA[buf] + r_ * ROWB + lc * 16,                           \
                       A + (size_t)(m0 + r_) * K + kk_ + lc * 8);               \
            cp_async16(sB[buf] + r_ * ROWB + lc * 16,                           \
                       B + (size_t)(n0 + r_) * K + kk_ + lc * 8);               \
        }                                                                       \
    } while (0)

    LOAD_STAGE(0, 0);
    CP_COMMIT();
    LOAD_STAGE(1, 1);
    CP_COMMIT();

    for (int kt = 0; kt < KT; kt++) {
        const int buf = kt % 3;
        if (kt + 1 < KT) CP_WAIT1(); else CP_WAIT0();
        __syncthreads();
        if (kt + 2 < KT) {
            LOAD_STAGE(kt + 2, (kt + 2) % 3);
            CP_COMMIT();
        }

#pragma unroll
        for (int ks = 0; ks < BK / 16; ks++) {
            uint32_t af[4][4];
#pragma unroll
            for (int mt = 0; mt < 4; mt++) {
                uint32_t addr = sA[buf] + (a_row + mt * 16) * ROWB +
                                (ks * 16 + a_koff) * 2;
                ldsm_x4(af[mt][0], af[mt][1], af[mt][2], af[mt][3], addr);
            }
            uint32_t bfr[4][2];
#pragma unroll
            for (int p = 0; p < 2; p++) {
                uint32_t r0, r1, r2, r3;
                uint32_t addr = sB[buf] + (b_row + p * 16) * ROWB +
                                (ks * 16 + b_koff) * 2;
                ldsm_x4(r0, r1, r2, r3, addr);
                bfr[2 * p][0] = r0; bfr[2 * p][1] = r1;
                bfr[2 * p + 1][0] = r2; bfr[2 * p + 1][1] = r3;
            }
#pragma unroll
            for (int mt = 0; mt < 4; mt++)
#pragma unroll
                for (int nt = 0; nt < 4; nt++)
                    mma16816(acc[mt][nt], af[mt], bfr[nt]);
        }
    }

    // epilogue: fp32 out + bias
#pragma unroll
    for (int mt = 0; mt < 4; mt++) {
        const int rm = m0 + warp_m * 64 + mt * 16 + (lane >> 2);
#pragma unroll
        for (int nt = 0; nt < 4; nt++) {
            const int cn = n0 + warp_n * 32 + nt * 8 + ((lane & 3) << 1);
            const float b0 = bias[cn], b1 = bias[cn + 1];
            float2 v0, v1;
            v0.x = acc[mt][nt][0] + b0;
            v0.y = acc[mt][nt][1] + b1;
            v1.x = acc[mt][nt][2] + b0;
            v1.y = acc[mt][nt][3] + b1;
            *(float2*)&C[(size_t)rm * HID + cn] = v0;
            *(float2*)&C[(size_t)(rm + 8) * HID + cn] = v1;
        }
    }
}

// ---------------------------------------------------------------------------
extern "C" void kernel_launch(void* const* d_in, const int* in_sizes, int n_in,
                              void* d_out, int out_size) {
    const float* node_in = (const float*)d_in[0];
    const int*   edges   = (const int*)d_in[1];
    const float* W_emb   = (const float*)d_in[2];
    const float* b_emb   = (const float*)d_in[3];
    const float* W1      = (const float*)d_in[4];
    const float* b1      = (const float*)d_in[5];
    const float* W2      = (const float*)d_in[6];
    const float* b2      = (const float*)d_in[7];
    const float* W3      = (const float*)d_in[8];
    const float* b3      = (const float*)d_in[9];
    float* out = (float*)d_out;

    __half* HA;  cudaGetSymbolAddress((void**)&HA, g_HA);
    float* XF;   cudaGetSymbolAddress((void**)&XF, g_XF);
    __half* W;   cudaGetSymbolAddress((void**)&W, g_W);
    __half* WaT; cudaGetSymbolAddress((void**)&WaT, g_WaT);
    float* c1;   cudaGetSymbolAddress((void**)&c1, g_c1);
    float* zero; cudaGetSymbolAddress((void**)&zero, g_zero);

    cudaFuncSetAttribute(gemm_hmma_kernel<HID>,
                         cudaFuncAttributeMaxDynamicSharedMemorySize, GSMEM);
    cudaFuncSetAttribute(gemm_hmma_kernel<F_NODE>,
                         cudaFuncAttributeMaxDynamicSharedMemorySize, GSMEM);

    prep_kernel<<<PREP_BLOCKS, 256>>>(edges, node_in, W_emb, b_emb, W1, W2, W3);

    dim3 gg(HID / BN, N_NODES / BM);       // (4, 64)
    dim3 sg(N_NODES / 4);                  // 2048 blocks

    // T1 = N @ W_a + c1   (K=128, fp32 out)
    gemm_hmma_kernel<F_NODE><<<gg, GTHR, GSMEM>>>(HA, WaT, c1, XF);
    // y1 = relu(A @ T1 + b1)  -> fp16
    spmm_kernel<true, true><<<sg, 256>>>(edges, XF, b1, HA);
    // T2 = y1 @ W2  (fp32 out)
    gemm_hmma_kernel<HID><<<gg, GTHR, GSMEM>>>(HA, W + WOFF_2, zero, XF);
    // y2 = relu(A @ T2 + b2)  -> fp16
    spmm_kernel<true, true><<<sg, 256>>>(edges, XF, b2, HA);
    // T3 = y2 @ W3  (fp32 out)
    gemm_hmma_kernel<HID><<<gg, GTHR, GSMEM>>>(HA, W + WOFF_3, zero, XF);
    // out = A @ T3 + b3   (fp32, no relu)
    spmm_kernel<false, false><<<sg, 256>>>(edges, XF, b3, out);
}

// round 14
// speedup vs baseline: 1.2434x; 1.2434x over previous
#include <cuda_runtime.h>
#include <cuda_fp16.h>
#include <cstdint>

#define N_NODES 8192
#define M_NBR   16
#define F_NODE  128
#define HID     512

// ---------------- scratch (__device__ globals; no allocations) ----------------
__device__ __half g_HA[N_NODES * HID];   // activation ping
__device__ __half g_HB[N_NODES * HID];   // activation pong
__device__ float  g_dinv[N_NODES];
#define WOFF_1 0
#define WOFF_2 (HID * HID)
#define WOFF_3 (2 * HID * HID)
__device__ __half g_W[3 * HID * HID];    // W1t/W2t/W3t, [N][K] K-major
__device__ __half g_WaT[HID * F_NODE];   // (W_emb@W1)^T, [512][128] K-major
__device__ float  g_c1[HID];             // b_emb @ W1

// ---------------- PTX helpers (compute_103-safe) ----------------
__device__ __forceinline__ uint32_t smem_to_u32(const void* p) {
    uint32_t a;
    asm("{ .reg .u64 t; cvta.to.shared.u64 t, %1; cvt.u32.u64 %0, t; }" : "=r"(a) : "l"(p));
    return a;
}
__device__ __forceinline__ void cp_async16(uint32_t saddr, const void* gptr) {
    asm volatile("cp.async.cg.shared.global [%0], [%1], 16;" :: "r"(saddr), "l"(gptr));
}
#define CP_COMMIT() asm volatile("cp.async.commit_group;" ::: "memory")
#define CP_WAIT0()  asm volatile("cp.async.wait_group 0;" ::: "memory")
#define CP_WAIT1()  asm volatile("cp.async.wait_group 1;" ::: "memory")

__device__ __forceinline__ void ldsm_x4(uint32_t& r0, uint32_t& r1, uint32_t& r2,
                                        uint32_t& r3, uint32_t addr) {
    asm volatile("ldmatrix.sync.aligned.m8n8.x4.shared.b16 {%0,%1,%2,%3}, [%4];"
                 : "=r"(r0), "=r"(r1), "=r"(r2), "=r"(r3) : "r"(addr));
}
__device__ __forceinline__ void mma16816(float* d, const uint32_t* a, const uint32_t* b) {
    asm volatile(
        "mma.sync.aligned.m16n8k16.row.col.f32.f16.f16.f32 "
        "{%0,%1,%2,%3}, {%4,%5,%6,%7}, {%8,%9}, {%0,%1,%2,%3};"
        : "+f"(d[0]), "+f"(d[1]), "+f"(d[2]), "+f"(d[3])
        : "r"(a[0]), "r"(a[1]), "r"(a[2]), "r"(a[3]), "r"(b[0]), "r"(b[1]));
}

// ---------------------------------------------------------------------------
// Fused preprocessing (one launch). Long-loop blocks FIRST so they start in
// wave 1 and overlap the rest:
//   [0,32)       WaT = (W_emb @ W1)^T  (fp16, [512][128] K-major)
//   [32,34)      c1 = b_emb @ W1
//   [34,66)      deg -> dinv
//   [66,1090)    node_in fp32 -> g_HA fp16
//   [1090,1858)  W1/W2/W3 transpose -> g_W
// ---------------------------------------------------------------------------
#define PREP_WA     32
#define PREP_C1     2
#define PREP_DEG    32
#define PREP_CONV   1024
#define PREP_W3     768
#define PREP_BLOCKS (PREP_WA + PREP_C1 + PREP_DEG + PREP_CONV + PREP_W3)

__device__ __forceinline__ void wconv_tile(const float* __restrict__ W, int K, int N,
                                           __half* __restrict__ o,
                                           int n0, int k0, int tx, int ty,
                                           float (*tile)[33]) {
#pragma unroll
    for (int r = 0; r < 4; r++) {
        int k = k0 + ty + r * 8;
        tile[ty + r * 8][tx] = W[(size_t)k * N + n0 + tx];
    }
    __syncthreads();
#pragma unroll
    for (int r = 0; r < 4; r++) {
        int n = ty + r * 8;
        o[(size_t)(n0 + n) * K + k0 + tx] = __float2half_rn(tile[tx][n]);
    }
}

__global__ __launch_bounds__(256) void prep_kernel(const int* __restrict__ idx,
                                                   const float* __restrict__ node_in,
                                                   const float* __restrict__ W_emb,
                                                   const float* __restrict__ b_emb,
                                                   const float* __restrict__ W1,
                                                   const float* __restrict__ W2,
                                                   const float* __restrict__ W3) {
    __shared__ float tile[32][33];
    const int b = blockIdx.x;
    const int tid = threadIdx.x;

    if (b < PREP_WA) {
        // WaT[n][k] = fp16( sum_m W_emb[k][m] * W1[m][n] ), k-tile of 4
        int k0 = b * 4;
        const int n = tid;           // and n+256
        float acc[4][2];
#pragma unroll
        for (int kk = 0; kk < 4; kk++) { acc[kk][0] = 0.0f; acc[kk][1] = 0.0f; }
        for (int m = 0; m < HID; m++) {
            float x0 = W1[(size_t)m * HID + n];
            float x1 = W1[(size_t)m * HID + n + 256];
#pragma unroll
            for (int kk = 0; kk < 4; kk++) {
                float w = __ldg(&W_emb[(size_t)(k0 + kk) * HID + m]);
                acc[kk][0] += w * x0;
                acc[kk][1] += w * x1;
            }
        }
#pragma unroll
        for (int kk = 0; kk < 4; kk++) {
            g_WaT[(size_t)n * F_NODE + k0 + kk] = __float2half_rn(acc[kk][0]);
            g_WaT[(size_t)(n + 256) * F_NODE + k0 + kk] = __float2half_rn(acc[kk][1]);
        }
    } else if (b < PREP_WA + PREP_C1) {
        int n = (b - PREP_WA) * 256 + tid;
        float c = 0.0f;
        for (int k = 0; k < HID; k++) c += b_emb[k] * W1[(size_t)k * HID + n];
        g_c1[n] = c;
    } else if (b < PREP_WA + PREP_C1 + PREP_DEG) {
        int i = (b - (PREP_WA + PREP_C1)) * 256 + tid;
        int cnt = 1;
#pragma unroll
        for (int k = 0; k < M_NBR; k++) cnt += (idx[i * M_NBR + k] >= 0) ? 1 : 0;
        g_dinv[i] = rsqrtf((float)cnt);
    } else if (b < PREP_WA + PREP_C1 + PREP_DEG + PREP_CONV) {
        int c4 = (b - (PREP_WA + PREP_C1 + PREP_DEG)) * 256 + tid;
        float4 v = ((const float4*)node_in)[c4];
        __half2 h0 = __floats2half2_rn(v.x, v.y);
        __half2 h1 = __floats2half2_rn(v.z, v.w);
        uint2 o;
        o.x = *(uint32_t*)&h0;
        o.y = *(uint32_t*)&h1;
        ((uint2*)g_HA)[c4] = o;
    } else {
        int t = b - (PREP_WA + PREP_C1 + PREP_DEG + PREP_CONV);
        int z = t >> 8;
        int tt = t & 255;
        int n0 = (tt & 15) * 32, k0 = (tt >> 4) * 32;
        const float* W = (z == 0) ? W1 : (z == 1) ? W2 : W3;
        wconv_tile(W, HID, HID, g_W + (size_t)z * HID * HID, n0, k0,
                   tid & 31, tid >> 5, tile);
    }
}

// ---------------------------------------------------------------------------
// SpMM plain (fp16 in/out, fp32 accumulate), branch-free gathers. (R9 kernel)
// ---------------------------------------------------------------------------
__global__ __launch_bounds__(256) void spmm_kernel(const int* __restrict__ idx,
                                                   const __half* __restrict__ Xin,
                                                   __half* __restrict__ Xout) {
    const int rloc = threadIdx.x >> 6;
    const int t64 = threadIdx.x & 63;
    const int i = blockIdx.x * 4 + rloc;

    __shared__ int s_j[4][M_NBR];
    __shared__ float s_dj[4][M_NBR];
    if (t64 < M_NBR) {
        int j = idx[i * M_NBR + t64];
        s_j[rloc][t64] = (j >= 0) ? j : 0;
        s_dj[rloc][t64] = (j >= 0) ? g_dinv[j] : 0.0f;
    }
    __syncthreads();

    const float di = g_dinv[i];
    float acc[8];
    {
        uint4 v = ((const uint4*)(Xin + (size_t)i * HID))[t64];
        float2 p0 = __half22float2(*(__half2*)&v.x);
        float2 p1 = __half22float2(*(__half2*)&v.y);
        float2 p2 = __half22float2(*(__half2*)&v.z);
        float2 p3 = __half22float2(*(__half2*)&v.w);
        acc[0] = p0.x * di; acc[1] = p0.y * di;
        acc[2] = p1.x * di; acc[3] = p1.y * di;
        acc[4] = p2.x * di; acc[5] = p2.y * di;
        acc[6] = p3.x * di; acc[7] = p3.y * di;
    }

#pragma unroll
    for (int k = 0; k < M_NBR; k++) {
        const int j = s_j[rloc][k];
        const float dj = s_dj[rloc][k];
        uint4 v = ((const uint4*)(Xin + (size_t)j * HID))[t64];
        float2 p0 = __half22float2(*(__half2*)&v.x);
        float2 p1 = __half22float2(*(__half2*)&v.y);
        float2 p2 = __half22float2(*(__half2*)&v.z);
        float2 p3 = __half22float2(*(__half2*)&v.w);
        acc[0] += dj * p0.x; acc[1] += dj * p0.y;
        acc[2] += dj * p1.x; acc[3] += dj * p1.y;
        acc[4] += dj * p2.x; acc[5] += dj * p2.y;
        acc[6] += dj * p3.x; acc[7] += dj * p3.y;
    }

    uint4 o;
    __half2 h0 = __floats2half2_rn(acc[0] * di, acc[1] * di);
    __half2 h1 = __floats2half2_rn(acc[2] * di, acc[3] * di);
    __half2 h2 = __floats2half2_rn(acc[4] * di, acc[5] * di);
    __half2 h3 = __floats2half2_rn(acc[6] * di, acc[7] * di);
    o.x = *(uint32_t*)&h0;
    o.y = *(uint32_t*)&h1;
    o.z = *(uint32_t*)&h2;
    o.w = *(uint32_t*)&h3;
    ((uint4*)(Xout + (size_t)i * HID))[t64] = o;
}

// ---------------------------------------------------------------------------
// SpMM + bias + relu (fp16 in/out): y = relu( di*(...) + bias )  (layer 1)
// ---------------------------------------------------------------------------
__global__ __launch_bounds__(256) void spmm_br_kernel(const int* __restrict__ idx,
                                                      const __half* __restrict__ Xin,
                                                      const float* __restrict__ bias,
                                                      __half* __restrict__ Xout) {
    const int rloc = threadIdx.x >> 6;
    const int t64 = threadIdx.x & 63;
    const int i = blockIdx.x * 4 + rloc;

    __shared__ int s_j[4][M_NBR];
    __shared__ float s_dj[4][M_NBR];
    if (t64 < M_NBR) {
        int j = idx[i * M_NBR + t64];
        s_j[rloc][t64] = (j >= 0) ? j : 0;
        s_dj[rloc][t64] = (j >= 0) ? g_dinv[j] : 0.0f;
    }
    __syncthreads();

    const float di = g_dinv[i];
    float acc[8];
    {
        uint4 v = ((const uint4*)(Xin + (size_t)i * HID))[t64];
        float2 p0 = __half22float2(*(__half2*)&v.x);
        float2 p1 = __half22float2(*(__half2*)&v.y);
        float2 p2 = __half22float2(*(__half2*)&v.z);
        float2 p3 = __half22float2(*(__half2*)&v.w);
        acc[0] = p0.x * di; acc[1] = p0.y * di;
        acc[2] = p1.x * di; acc[3] = p1.y * di;
        acc[4] = p2.x * di; acc[5] = p2.y * di;
        acc[6] = p3.x * di; acc[7] = p3.y * di;
    }

#pragma unroll
    for (int k = 0; k < M_NBR; k++) {
        const int j = s_j[rloc][k];
        const float dj = s_dj[rloc][k];
        uint4 v = ((const uint4*)(Xin + (size_t)j * HID))[t64];
        float2 p0 = __half22float2(*(__half2*)&v.x);
        float2 p1 = __half22float2(*(__half2*)&v.y);
        float2 p2 = __half22float2(*(__half2*)&v.z);
        float2 p3 = __half22float2(*(__half2*)&v.w);
        acc[0] += dj * p0.x; acc[1] += dj * p0.y;
        acc[2] += dj * p1.x; acc[3] += dj * p1.y;
        acc[4] += dj * p2.x; acc[5] += dj * p2.y;
        acc[6] += dj * p3.x; acc[7] += dj * p3.y;
    }

    const int c0 = t64 * 8;
    float4 bv0 = *(const float4*)&bias[c0];
    float4 bv1 = *(const float4*)&bias[c0 + 4];
    acc[0] = fmaxf(acc[0] * di + bv0.x, 0.0f);
    acc[1] = fmaxf(acc[1] * di + bv0.y, 0.0f);
    acc[2] = fmaxf(acc[2] * di + bv0.z, 0.0f);
    acc[3] = fmaxf(acc[3] * di + bv0.w, 0.0f);
    acc[4] = fmaxf(acc[4] * di + bv1.x, 0.0f);
    acc[5] = fmaxf(acc[5] * di + bv1.y, 0.0f);
    acc[6] = fmaxf(acc[6] * di + bv1.z, 0.0f);
    acc[7] = fmaxf(acc[7] * di + bv1.w, 0.0f);

    uint4 o;
    __half2 h0 = __floats2half2_rn(acc[0], acc[1]);
    __half2 h1 = __floats2half2_rn(acc[2], acc[3]);
    __half2 h2 = __floats2half2_rn(acc[4], acc[5]);
    __half2 h3 = __floats2half2_rn(acc[6], acc[7]);
    o.x = *(uint32_t*)&h0;
    o.y = *(uint32_t*)&h1;
    o.z = *(uint32_t*)&h2;
    o.w = *(uint32_t*)&h3;
    ((uint4*)(Xout + (size_t)i * HID))[t64] = o;
}

// ---------------------------------------------------------------------------
// fp16 HMMA GEMM (R9 kernel): C = A[MxK] * B[512xK]^T + bias (+relu)
// BM=128 BN=128 BK=64, 256 thr, warp grid 2x4, 3-stage cp.async.
// ---------------------------------------------------------------------------
#define BM 128
#define BN 128
#define BK 64
#define GTHR 256
#define ROWB 144
#define STAGE_B (2 * BM * ROWB)
#define GSMEM   (3 * STAGE_B)

template <int K, bool HALF_OUT>
__global__ __launch_bounds__(GTHR, 2)
void gemm_hmma_kernel(const __half* __restrict__ A,
                      const __half* __restrict__ B,
                      const float* __restrict__ bias,
                      void* __restrict__ Cout, int relu) {
    extern __shared__ __align__(16) char dynsmem[];

    const int tid = threadIdx.x;
    const int lane = tid & 31;
    const int wid = tid >> 5;
    const int warp_m = wid >> 2;
    const int warp_n = wid & 3;
    const int m0 = blockIdx.y * BM;
    const int n0 = blockIdx.x * BN;

    uint32_t sA[3], sB[3];
#pragma unroll
    for (int s = 0; s < 3; s++) {
        sA[s] = smem_to_u32(dynsmem + s * STAGE_B);
        sB[s] = sA[s] + BM * ROWB;
    }

    float acc[4][4][4];
#pragma unroll
    for (int i = 0; i < 4; i++)
#pragma unroll
        for (int j = 0; j < 4; j++)
#pragma unroll
            for (int q = 0; q < 4; q++) acc[i][j][q] = 0.0f;

    constexpr int KT = K / BK;

    const int mat = lane >> 3;
    const int mrow = lane & 7;
    const int a_row = warp_m * 64 + ((mat & 1) << 3) + mrow;
    const int a_koff = (mat >> 1) << 3;
    const int b_row = warp_n * 32 + ((mat >> 1) << 3) + mrow;
    const int b_koff = (mat & 1) << 3;

    const int lr = tid >> 3;
    const int lc = tid & 7;

#define LOAD_STAGE(kt, buf)                                                     \
    do {                                                                        \
        const int kk_ = (kt) * BK;                                              \
        _Pragma("unroll")                                                       \
        for (int s_ = 0; s_ < 4; s_++) {                                        \
            int r_ = lr + s_ * 32;                                              \
            cp_async16(sA[buf] + r_ * ROWB + lc * 16,                           \
                       A + (size_t)(m0 + r_) * K + kk_ + lc * 8);               \
            cp_async16(sB[buf] + r_ * ROWB + lc * 16,                           \
                       B + (size_t)(n0 + r_) * K + kk_ + lc * 8);               \
        }                                                                       \
    } while (0)

    LOAD_STAGE(0, 0);
    CP_COMMIT();
    LOAD_STAGE(1, 1);
    CP_COMMIT();

    for (int kt = 0; kt < KT; kt++) {
        const int buf = kt % 3;
        if (kt + 1 < KT) CP_WAIT1(); else CP_WAIT0();
        __syncthreads();
        if (kt + 2 < KT) {
            LOAD_STAGE(kt + 2, (kt + 2) % 3);
            CP_COMMIT();
        }

#pragma unroll
        for (int ks = 0; ks < BK / 16; ks++) {
            uint32_t af[4][4];
#pragma unroll
            for (int mt = 0; mt < 4; mt++) {
                uint32_t addr = sA[buf] + (a_row + mt * 16) * ROWB +
                                (ks * 16 + a_koff) * 2;
                ldsm_x4(af[mt][0], af[mt][1], af[mt][2], af[mt][3], addr);
            }
            uint32_t bfr[4][2];
#pragma unroll
            for (int p = 0; p < 2; p++) {
                uint32_t r0, r1, r2, r3;
                uint32_t addr = sB[buf] + (b_row + p * 16) * ROWB +
                                (ks * 16 + b_koff) * 2;
                ldsm_x4(r0, r1, r2, r3, addr);
                bfr[2 * p][0] = r0; bfr[2 * p][1] = r1;
                bfr[2 * p + 1][0] = r2; bfr[2 * p + 1][1] = r3;
            }
#pragma unroll
            for (int mt = 0; mt < 4; mt++)
#pragma unroll
                for (int nt = 0; nt < 4; nt++)
                    mma16816(acc[mt][nt], af[mt], bfr[nt]);
        }
    }

    // epilogue
#pragma unroll
    for (int mt = 0; mt < 4; mt++) {
        const int rm = m0 + warp_m * 64 + mt * 16 + (lane >> 2);
#pragma unroll
        for (int nt = 0; nt < 4; nt++) {
            const int cn = n0 + warp_n * 32 + nt * 8 + ((lane & 3) << 1);
            const float b0 = bias[cn], b1 = bias[cn + 1];
            float2 v0, v1;
            v0.x = acc[mt][nt][0] + b0;
            v0.y = acc[mt][nt][1] + b1;
            v1.x = acc[mt][nt][2] + b0;
            v1.y = acc[mt][nt][3] + b1;
            if (relu) {
                v0.x = fmaxf(v0.x, 0.0f); v0.y = fmaxf(v0.y, 0.0f);
                v1.x = fmaxf(v1.x, 0.0f); v1.y = fmaxf(v1.y, 0.0f);
            }
            if (HALF_OUT) {
                __half* Ch = (__half*)Cout;
                *(__half2*)&Ch[(size_t)rm * HID + cn] = __floats2half2_rn(v0.x, v0.y);
                *(__half2*)&Ch[(size_t)(rm + 8) * HID + cn] = __floats2half2_rn(v1.x, v1.y);
            } else {
                float* Cf = (float*)Cout;
                *(float2*)&Cf[(size_t)rm * HID + cn] = v0;
                *(float2*)&Cf[(size_t)(rm + 8) * HID + cn] = v1;
            }
        }
    }
}

// ---------------------------------------------------------------------------
extern "C" void kernel_launch(void* const* d_in, const int* in_sizes, int n_in,
                              void* d_out, int out_size) {
    const float* node_in = (const float*)d_in[0];
    const int*   edges   = (const int*)d_in[1];
    const float* W_emb   = (const float*)d_in[2];
    const float* b_emb   = (const float*)d_in[3];
    const float* W1      = (const float*)d_in[4];
    const float* b1      = (const float*)d_in[5];
    const float* W2      = (const float*)d_in[6];
    const float* b2      = (const float*)d_in[7];
    const float* W3      = (const float*)d_in[8];
    const float* b3      = (const float*)d_in[9];
    float* out = (float*)d_out;

    __half* HA;  cudaGetSymbolAddress((void**)&HA, g_HA);
    __half* HB;  cudaGetSymbolAddress((void**)&HB, g_HB);
    __half* W;   cudaGetSymbolAddress((void**)&W, g_W);
    __half* WaT; cudaGetSymbolAddress((void**)&WaT, g_WaT);
    float* c1;   cudaGetSymbolAddress((void**)&c1, g_c1);

    cudaFuncSetAttribute(gemm_hmma_kernel<HID, true>,
                         cudaFuncAttributeMaxDynamicSharedMemorySize, GSMEM);
    cudaFuncSetAttribute(gemm_hmma_kernel<HID, false>,
                         cudaFuncAttributeMaxDynamicSharedMemorySize, GSMEM);
    cudaFuncSetAttribute(gemm_hmma_kernel<F_NODE, true>,
                         cudaFuncAttributeMaxDynamicSharedMemorySize, GSMEM);

    prep_kernel<<<PREP_BLOCKS, 256>>>(edges, node_in, W_emb, b_emb, W1, W2, W3);

    dim3 gg(HID / BN, N_NODES / BM);       // (4, 64)
    dim3 sg(N_NODES / 4);                  // 2048 blocks

    // layer 1 via algebra: T1 = x0 @ W_a + c1  (K=128, fp16 out, no relu)
    gemm_hmma_kernel<F_NODE, true><<<gg, GTHR, GSMEM>>>(HA, WaT, c1, HB, 0);
    // y1 = relu(A @ T1 + b1) -> fp16
    spmm_br_kernel<<<sg, 256>>>(edges, HB, b1, HA);
    // layer 2 (R9 form): z = A @ y1 ; x2 = relu(z @ W2 + b2)
    spmm_kernel<<<sg, 256>>>(edges, HA, HB);
    gemm_hmma_kernel<HID, true><<<gg, GTHR, GSMEM>>>(HB, W + WOFF_2, b2, HA, 1);
    // layer 3: z = A @ x2 ; out = z @ W3 + b3 (fp32)
    spmm_kernel<<<sg, 256>>>(edges, HA, HB);
    gemm_hmma_kernel<HID, false><<<gg, GTHR, GSMEM>>>(HB, W + WOFF_3, b3, out, 0);
}

// round 15
// speedup vs baseline: 1.6318x; 1.3123x over previous
#include <cuda_runtime.h>
#include <cuda_fp16.h>
#include <cstdint>

#define N_NODES 8192
#define M_NBR   16
#define F_NODE  128
#define HID     512

// ---------------- scratch (__device__ globals; no allocations) ----------------
__device__ __half g_HA[N_NODES * HID];   // activation ping
__device__ __half g_HB[N_NODES * HID];   // activation pong
__device__ float  g_dinv[N_NODES];
#define WOFF_1 0
#define WOFF_2 (HID * HID)
#define WOFF_3 (2 * HID * HID)
#define WOFF_E (3 * HID * HID)
__device__ __half g_W[3 * HID * HID + HID * F_NODE];

// ---------------- PTX helpers (compute_103-safe) ----------------
__device__ __forceinline__ uint32_t smem_to_u32(const void* p) {
    uint32_t a;
    asm("{ .reg .u64 t; cvta.to.shared.u64 t, %1; cvt.u32.u64 %0, t; }" : "=r"(a) : "l"(p));
    return a;
}
__device__ __forceinline__ void cp_async16(uint32_t saddr, const void* gptr) {
    asm volatile("cp.async.cg.shared.global [%0], [%1], 16;" :: "r"(saddr), "l"(gptr));
}
#define CP_COMMIT() asm volatile("cp.async.commit_group;" ::: "memory")
#define CP_WAIT0()  asm volatile("cp.async.wait_group 0;" ::: "memory")
#define CP_WAIT1()  asm volatile("cp.async.wait_group 1;" ::: "memory")

__device__ __forceinline__ void ldsm_x4(uint32_t& r0, uint32_t& r1, uint32_t& r2,
                                        uint32_t& r3, uint32_t addr) {
    asm volatile("ldmatrix.sync.aligned.m8n8.x4.shared.b16 {%0,%1,%2,%3}, [%4];"
                 : "=r"(r0), "=r"(r1), "=r"(r2), "=r"(r3) : "r"(addr));
}
__device__ __forceinline__ void mma16816(float* d, const uint32_t* a, const uint32_t* b) {
    asm volatile(
        "mma.sync.aligned.m16n8k16.row.col.f32.f16.f16.f32 "
        "{%0,%1,%2,%3}, {%4,%5,%6,%7}, {%8,%9}, {%0,%1,%2,%3};"
        : "+f"(d[0]), "+f"(d[1]), "+f"(d[2]), "+f"(d[3])
        : "r"(a[0]), "r"(a[1]), "r"(a[2]), "r"(a[3]), "r"(b[0]), "r"(b[1]));
}

// ---------------------------------------------------------------------------
// Fused preprocessing (one launch):
//   [0,32)      deg -> dinv
//   [32,1056)   node_in fp32 -> g_HA fp16
//   [1056,1120) W_emb transpose
//   [1120,1888) W1/W2/W3 transpose
// ---------------------------------------------------------------------------
#define PREP_DEG    32
#define PREP_CONV   1024
#define PREP_WE     64
#define PREP_W3     768
#define PREP_BLOCKS (PREP_DEG + PREP_CONV + PREP_WE + PREP_W3)

__device__ __forceinline__ void wconv_tile(const float* __restrict__ W, int K, int N,
                                           __half* __restrict__ o,
                                           int n0, int k0, int tx, int ty,
                                           float (*tile)[33]) {
#pragma unroll
    for (int r = 0; r < 4; r++) {
        int k = k0 + ty + r * 8;
        tile[ty + r * 8][tx] = W[(size_t)k * N + n0 + tx];
    }
    __syncthreads();
#pragma unroll
    for (int r = 0; r < 4; r++) {
        int n = ty + r * 8;
        o[(size_t)(n0 + n) * K + k0 + tx] = __float2half_rn(tile[tx][n]);
    }
}

__global__ __launch_bounds__(256) void prep_kernel(const int* __restrict__ idx,
                                                   const float* __restrict__ node_in,
                                                   const float* __restrict__ W_emb,
                                                   const float* __restrict__ W1,
                                                   const float* __restrict__ W2,
                                                   const float* __restrict__ W3) {
    __shared__ float tile[32][33];
    const int b = blockIdx.x;
    const int tid = threadIdx.x;

    if (b < PREP_DEG) {
        int i = b * 256 + tid;
        int cnt = 1;
#pragma unroll
        for (int k = 0; k < M_NBR; k++) cnt += (idx[i * M_NBR + k] >= 0) ? 1 : 0;
        g_dinv[i] = rsqrtf((float)cnt);
    } else if (b < PREP_DEG + PREP_CONV) {
        int c4 = (b - PREP_DEG) * 256 + tid;
        float4 v = ((const float4*)node_in)[c4];
        __half2 h0 = __floats2half2_rn(v.x, v.y);
        __half2 h1 = __floats2half2_rn(v.z, v.w);
        uint2 o;
        o.x = *(uint32_t*)&h0;
        o.y = *(uint32_t*)&h1;
        ((uint2*)g_HA)[c4] = o;
    } else if (b < PREP_DEG + PREP_CONV + PREP_WE) {
        int t = b - (PREP_DEG + PREP_CONV);
        int n0 = (t & 15) * 32, k0 = (t >> 4) * 32;
        wconv_tile(W_emb, F_NODE, HID, g_W + WOFF_E, n0, k0, tid & 31, tid >> 5, tile);
    } else {
        int t = b - (PREP_DEG + PREP_CONV + PREP_WE);
        int z = t >> 8;
        int tt = t & 255;
        int n0 = (tt & 15) * 32, k0 = (tt >> 4) * 32;
        const float* W = (z == 0) ? W1 : (z == 1) ? W2 : W3;
        wconv_tile(W, HID, HID, g_W + (size_t)z * HID * HID, n0, k0,
                   tid & 31, tid >> 5, tile);
    }
}

// ---------------------------------------------------------------------------
// SpMM (fp16 in/out, fp32 accumulate), branch-free gathers.
// 256 threads = 2 rows x 128 lanes; 8 B (uint2, 4 halves) per lane.
// Small loads (2 regs each) let ptxas front-batch all 17 gathers (MLP=17).
// ---------------------------------------------------------------------------
__global__ __launch_bounds__(256) void spmm_kernel(const int* __restrict__ idx,
                                                   const __half* __restrict__ Xin,
                                                   __half* __restrict__ Xout) {
    const int rloc = threadIdx.x >> 7;           // 0..1
    const int t128 = threadIdx.x & 127;          // lane within row
    const int i = blockIdx.x * 2 + rloc;

    __shared__ int s_j[2][M_NBR];
    __shared__ float s_dj[2][M_NBR];
    if (t128 < M_NBR) {
        int j = idx[i * M_NBR + t128];
        s_j[rloc][t128] = (j >= 0) ? j : 0;
        s_dj[rloc][t128] = (j >= 0) ? g_dinv[j] : 0.0f;
    }
    __syncthreads();

    const float di = g_dinv[i];
    float acc0, acc1, acc2, acc3;
    {
        uint2 v = ((const uint2*)(Xin + (size_t)i * HID))[t128];
        float2 p0 = __half22float2(*(__half2*)&v.x);
        float2 p1 = __half22float2(*(__half2*)&v.y);
        acc0 = p0.x * di; acc1 = p0.y * di;
        acc2 = p1.x * di; acc3 = p1.y * di;
    }

#pragma unroll
    for (int k = 0; k < M_NBR; k++) {
        const int j = s_j[rloc][k];
        const float dj = s_dj[rloc][k];
        uint2 v = ((const uint2*)(Xin + (size_t)j * HID))[t128];
        float2 p0 = __half22float2(*(__half2*)&v.x);
        float2 p1 = __half22float2(*(__half2*)&v.y);
        acc0 += dj * p0.x; acc1 += dj * p0.y;
        acc2 += dj * p1.x; acc3 += dj * p1.y;
    }

    uint2 o;
    __half2 h0 = __floats2half2_rn(acc0 * di, acc1 * di);
    __half2 h1 = __floats2half2_rn(acc2 * di, acc3 * di);
    o.x = *(uint32_t*)&h0;
    o.y = *(uint32_t*)&h1;
    ((uint2*)(Xout + (size_t)i * HID))[t128] = o;
}

// ---------------------------------------------------------------------------
// fp16 HMMA GEMM (R9 kernel): C[M x 512] = A[M x K] * B[512 x K]^T + bias (+relu)
// BM=128 BN=128 BK=64, 256 thr, warp grid 2x4 (warp tile 64x32),
// 3-stage cp.async, one __syncthreads per k-iteration, 144 B smem rows.
// ---------------------------------------------------------------------------
#define BM 128
#define BN 128
#define BK 64
#define GTHR 256
#define ROWB 144
#define STAGE_B (2 * BM * ROWB)
#define GSMEM   (3 * STAGE_B)

template <int K, bool HALF_OUT>
__global__ __launch_bounds__(GTHR, 2)
void gemm_hmma_kernel(const __half* __restrict__ A,
                      const __half* __restrict__ B,
                      const float* __restrict__ bias,
                      void* __restrict__ Cout, int relu) {
    extern __shared__ __align__(16) char dynsmem[];

    const int tid = threadIdx.x;
    const int lane = tid & 31;
    const int wid = tid >> 5;
    const int warp_m = wid >> 2;
    const int warp_n = wid & 3;
    const int m0 = blockIdx.y * BM;
    const int n0 = blockIdx.x * BN;

    uint32_t sA[3], sB[3];
#pragma unroll
    for (int s = 0; s < 3; s++) {
        sA[s] = smem_to_u32(dynsmem + s * STAGE_B);
        sB[s] = sA[s] + BM * ROWB;
    }

    float acc[4][4][4];
#pragma unroll
    for (int i = 0; i < 4; i++)
#pragma unroll
        for (int j = 0; j < 4; j++)
#pragma unroll
            for (int q = 0; q < 4; q++) acc[i][j][q] = 0.0f;

    constexpr int KT = K / BK;

    const int mat = lane >> 3;
    const int mrow = lane & 7;
    const int a_row = warp_m * 64 + ((mat & 1) << 3) + mrow;
    const int a_koff = (mat >> 1) << 3;
    const int b_row = warp_n * 32 + ((mat >> 1) << 3) + mrow;
    const int b_koff = (mat & 1) << 3;

    const int lr = tid >> 3;
    const int lc = tid & 7;

#define LOAD_STAGE(kt, buf)                                                     \
    do {                                                                        \
        const int kk_ = (kt) * BK;                                              \
        _Pragma("unroll")                                                       \
        for (int s_ = 0; s_ < 4; s_++) {                                        \
            int r_ = lr + s_ * 32;                                              \
            cp_async16(sA[buf] + r_ * ROWB + lc * 16,                           \
                       A + (size_t)(m0 + r_) * K + kk_ + lc * 8);               \
            cp_async16(sB[buf] + r_ * ROWB + lc * 16,                           \
                       B + (size_t)(n0 + r_) * K + kk_ + lc * 8);               \
        }                                                                       \
    } while (0)

    LOAD_STAGE(0, 0);
    CP_COMMIT();
    LOAD_STAGE(1, 1);
    CP_COMMIT();

    for (int kt = 0; kt < KT; kt++) {
        const int buf = kt % 3;
        if (kt + 1 < KT) CP_WAIT1(); else CP_WAIT0();
        __syncthreads();
        if (kt + 2 < KT) {
            LOAD_STAGE(kt + 2, (kt + 2) % 3);
            CP_COMMIT();
        }

#pragma unroll
        for (int ks = 0; ks < BK / 16; ks++) {
            uint32_t af[4][4];
#pragma unroll
            for (int mt = 0; mt < 4; mt++) {
                uint32_t addr = sA[buf] + (a_row + mt * 16) * ROWB +
                                (ks * 16 + a_koff) * 2;
                ldsm_x4(af[mt][0], af[mt][1], af[mt][2], af[mt][3], addr);
            }
            uint32_t bfr[4][2];
#pragma unroll
            for (int p = 0; p < 2; p++) {
                uint32_t r0, r1, r2, r3;
                uint32_t addr = sB[buf] + (b_row + p * 16) * ROWB +
                                (ks * 16 + b_koff) * 2;
                ldsm_x4(r0, r1, r2, r3, addr);
                bfr[2 * p][0] = r0; bfr[2 * p][1] = r1;
                bfr[2 * p + 1][0] = r2; bfr[2 * p + 1][1] = r3;
            }
#pragma unroll
            for (int mt = 0; mt < 4; mt++)
#pragma unroll
                for (int nt = 0; nt < 4; nt++)
                    mma16816(acc[mt][nt], af[mt], bfr[nt]);
        }
    }

    // epilogue
#pragma unroll
    for (int mt = 0; mt < 4; mt++) {
        const int rm = m0 + warp_m * 64 + mt * 16 + (lane >> 2);
#pragma unroll
        for (int nt = 0; nt < 4; nt++) {
            const int cn = n0 + warp_n * 32 + nt * 8 + ((lane & 3) << 1);
            const float b0 = bias[cn], b1 = bias[cn + 1];
            float2 v0, v1;
            v0.x = acc[mt][nt][0] + b0;
            v0.y = acc[mt][nt][1] + b1;
            v1.x = acc[mt][nt][2] + b0;
            v1.y = acc[mt][nt][3] + b1;
            if (relu) {
                v0.x = fmaxf(v0.x, 0.0f); v0.y = fmaxf(v0.y, 0.0f);
                v1.x = fmaxf(v1.x, 0.0f); v1.y = fmaxf(v1.y, 0.0f);
            }
            if (HALF_OUT) {
                __half* Ch = (__half*)Cout;
                *(__half2*)&Ch[(size_t)rm * HID + cn] = __floats2half2_rn(v0.x, v0.y);
                *(__half2*)&Ch[(size_t)(rm + 8) * HID + cn] = __floats2half2_rn(v1.x, v1.y);
            } else {
                float* Cf = (float*)Cout;
                *(float2*)&Cf[(size_t)rm * HID + cn] = v0;
                *(float2*)&Cf[(size_t)(rm + 8) * HID + cn] = v1;
            }
        }
    }
}

// ---------------------------------------------------------------------------
extern "C" void kernel_launch(void* const* d_in, const int* in_sizes, int n_in,
                              void* d_out, int out_size) {
    const float* node_in = (const float*)d_in[0];
    const int*   edges   = (const int*)d_in[1];
    const float* W_emb   = (const float*)d_in[2];
    const float* b_emb   = (const float*)d_in[3];
    const float* W1      = (const float*)d_in[4];
    const float* b1      = (const float*)d_in[5];
    const float* W2      = (const float*)d_in[6];
    const float* b2      = (const float*)d_in[7];
    const float* W3      = (const float*)d_in[8];
    const float* b3      = (const float*)d_in[9];
    float* out = (float*)d_out;

    __half* HA; cudaGetSymbolAddress((void**)&HA, g_HA);
    __half* HB; cudaGetSymbolAddress((void**)&HB, g_HB);
    __half* W;  cudaGetSymbolAddress((void**)&W, g_W);

    cudaFuncSetAttribute(gemm_hmma_kernel<HID, true>,
                         cudaFuncAttributeMaxDynamicSharedMemorySize, GSMEM);
    cudaFuncSetAttribute(gemm_hmma_kernel<HID, false>,
                         cudaFuncAttributeMaxDynamicSharedMemorySize, GSMEM);
    cudaFuncSetAttribute(gemm_hmma_kernel<F_NODE, true>,
                         cudaFuncAttributeMaxDynamicSharedMemorySize, GSMEM);

    prep_kernel<<<PREP_BLOCKS, 256>>>(edges, node_in, W_emb, W1, W2, W3);

    dim3 gg(HID / BN, N_NODES / BM);  // (4, 64)
    dim3 sg(N_NODES / 2);             // 4096 blocks

    // embed: HB = node_in @ W_emb + b_emb  (fp16 out)
    gemm_hmma_kernel<F_NODE, true><<<gg, GTHR, GSMEM>>>(HA, W + WOFF_E, b_emb, HB, 0);
    // layer 1
    spmm_kernel<<<sg, 256>>>(edges, HB, HA);
    gemm_hmma_kernel<HID, true><<<gg, GTHR, GSMEM>>>(HA, W + WOFF_1, b1, HB, 1);
    // layer 2
    spmm_kernel<<<sg, 256>>>(edges, HB, HA);
    gemm_hmma_kernel<HID, true><<<gg, GTHR, GSMEM>>>(HA, W + WOFF_2, b2, HB, 1);
    // layer 3 -> fp32 out
    spmm_kernel<<<sg, 256>>>(edges, HB, HA);
    gemm_hmma_kernel<HID, false><<<gg, GTHR, GSMEM>>>(HA, W + WOFF_3, b3, out, 0);
}